// round 8
// baseline (speedup 1.0000x reference)
#include <cuda_runtime.h>
#include <cuda_bf16.h>
#include <math.h>
#include <stdint.h>

#define NN 50000
#define EE 500000
#define CLAMPV 5.0f
#define K3 384          // K' = 3 * 128 (hi/lo/hi interleave)
#define KC 64           // k' per smem chunk
#define NCHUNK 6
#define PITCH 72        // smem pitch (bf16): 144B rows, conflict-free quad pattern
#define EPAD  500096    // EE rounded up to 128

// ---------------- scratch ----------------------------------------------------
__device__ float g_Qh[NN * 128];
__device__ float g_Kh[NN * 128];
__device__ float g_Vh[NN * 128];
__device__ float g_eexp[(size_t)EE * 8];
__device__ float g_denom[NN * 8];
__device__ float g_rowV[NN * 128];
__device__ __align__(16) __nv_bfloat16 g_Ae[(size_t)EPAD * K3];  // edge_attr tri-split
__device__ __align__(16) __nv_bfloat16 g_Be[256 * K3];           // WE [n][k'] tri-split

// ---------------- helpers ----------------------------------------------------
__device__ __forceinline__ void red_add_v4(float* addr, float a, float b, float c, float d) {
    asm volatile("red.global.add.v4.f32 [%0], {%1,%2,%3,%4};"
                 :: "l"(addr), "f"(a), "f"(b), "f"(c), "f"(d) : "memory");
}
__device__ __forceinline__ void mma_bf16(float& c0, float& c1, float& c2, float& c3,
                                         unsigned a0, unsigned a1, unsigned a2, unsigned a3,
                                         unsigned b0, unsigned b1) {
    asm volatile(
        "mma.sync.aligned.m16n8k16.row.col.f32.bf16.bf16.f32 "
        "{%0,%1,%2,%3}, {%4,%5,%6,%7}, {%8,%9}, {%0,%1,%2,%3};\n"
        : "+f"(c0), "+f"(c1), "+f"(c2), "+f"(c3)
        : "r"(a0), "r"(a1), "r"(a2), "r"(a3), "r"(b0), "r"(b1));
}

// ---------------- zero scratch ------------------------------------------------
__global__ void zero_kernel() {
    int stride = gridDim.x * blockDim.x;
    int total = NN * 128 + NN * 8;
    for (int i = blockIdx.x * blockDim.x + threadIdx.x; i < total; i += stride) {
        if (i < NN * 128) g_rowV[i] = 0.f;
        else              g_denom[i - NN * 128] = 0.f;
    }
}

// ---------------- convert edge_attr: fp32[rows][128] -> bf16 tri [EPAD][384] -
__global__ void convert_rows(const float* __restrict__ in, __nv_bfloat16* __restrict__ out,
                             int rows, int padRows) {
    int t = blockIdx.x * blockDim.x + threadIdx.x;
    if (t >= padRows * 16) return;
    int row = t >> 4, j = t & 15;
    union { __nv_bfloat16 h[24]; uint4 v[3]; } o;
    if (row < rows) {
        const float4* p = (const float4*)(in + (size_t)row * 128 + j * 8);
        float4 v0 = p[0], v1 = p[1];
        float f[8] = {v0.x, v0.y, v0.z, v0.w, v1.x, v1.y, v1.z, v1.w};
        #pragma unroll
        for (int k = 0; k < 8; k++) {
            float a = f[k];
            __nv_bfloat16 ah = __float2bfloat16(a);
            __nv_bfloat16 al = __float2bfloat16(a - __bfloat162float(ah));
            o.h[3 * k] = ah; o.h[3 * k + 1] = al; o.h[3 * k + 2] = ah;
        }
    } else {
        o.v[0] = make_uint4(0, 0, 0, 0);
        o.v[1] = make_uint4(0, 0, 0, 0);
        o.v[2] = make_uint4(0, 0, 0, 0);
    }
    uint4* q = (uint4*)(out + (size_t)row * K3 + j * 24);
    q[0] = o.v[0]; q[1] = o.v[1]; q[2] = o.v[2];
}

// ---------------- convert WE: fp32[128][256] -> bf16 tri [256][384] ----------
__global__ void convert_W(const float* __restrict__ in, __nv_bfloat16* __restrict__ out, int Nout) {
    int t = blockIdx.x * blockDim.x + threadIdx.x;
    if (t >= 128 * Nout) return;
    int k = t / Nout, n = t % Nout;
    float b = in[(size_t)k * Nout + n];
    __nv_bfloat16 bh = __float2bfloat16(b);
    __nv_bfloat16 bl = __float2bfloat16(b - __bfloat162float(bh));
    out[(size_t)n * K3 + 3 * k + 0] = bh;
    out[(size_t)n * K3 + 3 * k + 1] = bh;
    out[(size_t)n * K3 + 3 * k + 2] = bl;
}

// ---------------- node GEMM (fp32, proven) ------------------------------------
__global__ __launch_bounds__(256) void node_gemm(
    const float* __restrict__ x,
    const float* __restrict__ WQ, const float* __restrict__ bQ,
    const float* __restrict__ WK, const float* __restrict__ bK,
    const float* __restrict__ WV, const float* __restrict__ bV,
    float* __restrict__ d_out)
{
    const int which = blockIdx.y;
    const float* W    = (which == 0) ? WQ : (which == 1) ? WK : WV;
    const float* bias = (which == 0) ? bQ : (which == 1) ? bK : bV;
    float* out        = (which == 0) ? g_Qh : (which == 1) ? g_Kh : g_Vh;

    __shared__ float As[64 * 16];
    __shared__ float Bs[16 * 128];

    const int tid = threadIdx.x;
    const int tx = tid & 15, ty = tid >> 4;
    const int m0 = blockIdx.x * 64;

    const int ar = tid >> 2;
    const int ac = (tid & 3) * 4;
    const int brow = tid >> 4;
    const int bcol = (tid & 15) * 8;

    float acc[4][8];
    #pragma unroll
    for (int i = 0; i < 4; i++)
        #pragma unroll
        for (int j = 0; j < 8; j++) acc[i][j] = 0.f;

    for (int k0 = 0; k0 < 128; k0 += 16) {
        float4 av = make_float4(0.f, 0.f, 0.f, 0.f);
        int m = m0 + ar;
        if (m < NN) av = *(const float4*)&x[(size_t)m * 128 + k0 + ac];
        *(float4*)&As[ar * 16 + ac] = av;
        *(float4*)&Bs[brow * 128 + bcol]     = *(const float4*)&W[(size_t)(k0 + brow) * 128 + bcol];
        *(float4*)&Bs[brow * 128 + bcol + 4] = *(const float4*)&W[(size_t)(k0 + brow) * 128 + bcol + 4];
        __syncthreads();
        #pragma unroll
        for (int k = 0; k < 16; k++) {
            float a[4], b[8];
            #pragma unroll
            for (int i = 0; i < 4; i++) a[i] = As[(ty * 4 + i) * 16 + k];
            #pragma unroll
            for (int j = 0; j < 8; j++) b[j] = Bs[k * 128 + tx * 8 + j];
            #pragma unroll
            for (int i = 0; i < 4; i++)
                #pragma unroll
                for (int j = 0; j < 8; j++)
                    acc[i][j] = fmaf(a[i], b[j], acc[i][j]);
        }
        __syncthreads();
    }

    #pragma unroll
    for (int i = 0; i < 4; i++) {
        int m = m0 + ty * 4 + i;
        if (m >= NN) continue;
        #pragma unroll
        for (int j = 0; j < 8; j++) {
            int c = tx * 8 + j;
            float v = acc[i][j] + bias[c];
            out[(size_t)m * 128 + c] = v;
            if (which == 0) d_out[(size_t)m * 128 + c] = v;
        }
    }
}

// ---------------- edge GEMM (bf16 mma.sync, 16 warps, 32x32 warp tiles) -------
// CTA tile 128(M) x 128(N). n-half folded into grid.x LSB for L2 reuse of A.
// Double buffer: LDG(ch+1) -> MMA(ch) -> STS(ch+1). No lambdas, no prefetch
// arrays, no outer unroll (the round-5/6 16ms pathology).
__global__ __launch_bounds__(512) void edge_gemm_tc(
    const __nv_bfloat16* __restrict__ A,
    const __nv_bfloat16* __restrict__ B,
    const float* __restrict__ bias,
    const int* __restrict__ edge_index,
    const float* __restrict__ Aw,
    float* __restrict__ d_out)
{
    extern __shared__ __align__(16) char smem_raw[];
    __nv_bfloat16* AsB = (__nv_bfloat16*)smem_raw;   // [2][128*PITCH]
    __nv_bfloat16* BsB = AsB + 2 * 128 * PITCH;      // [2][128*PITCH]

    const int tid = threadIdx.x, lane = tid & 31, wrp = tid >> 5;   // 16 warps
    const int g = lane >> 2, tg = lane & 3;
    const int m0 = (blockIdx.x >> 1) * 128;
    const int half = blockIdx.x & 1;
    const int n0 = half * 128;
    const int warp_m = (wrp & 3) * 32;
    const int warp_n = (wrp >> 2) * 32;

    // loader mapping: 512 threads, 1024 uint4 per operand chunk -> 2 each
    const int lrow = tid >> 3;          // 0..63
    const int lseg = tid & 7;           // 0..7
    const __nv_bfloat16* Arow0 = A + (size_t)(m0 + lrow) * K3 + lseg * 8;
    const __nv_bfloat16* Arow1 = A + (size_t)(m0 + lrow + 64) * K3 + lseg * 8;
    const __nv_bfloat16* Brow0 = B + (size_t)(n0 + lrow) * K3 + lseg * 8;
    const __nv_bfloat16* Brow1 = B + (size_t)(n0 + lrow + 64) * K3 + lseg * 8;
    __nv_bfloat16* sA0 = &AsB[lrow * PITCH + lseg * 8];
    __nv_bfloat16* sA1 = &AsB[(lrow + 64) * PITCH + lseg * 8];
    __nv_bfloat16* sB0 = &BsB[lrow * PITCH + lseg * 8];
    __nv_bfloat16* sB1 = &BsB[(lrow + 64) * PITCH + lseg * 8];

    float c[2][4][4];
    #pragma unroll
    for (int mt = 0; mt < 2; mt++)
        #pragma unroll
        for (int nt = 0; nt < 4; nt++)
            #pragma unroll
            for (int q = 0; q < 4; q++) c[mt][nt][q] = 0.f;

    // prologue: stage chunk 0
    {
        uint4 a0 = *(const uint4*)Arow0;
        uint4 a1 = *(const uint4*)Arow1;
        uint4 b0 = *(const uint4*)Brow0;
        uint4 b1 = *(const uint4*)Brow1;
        *(uint4*)sA0 = a0; *(uint4*)sA1 = a1;
        *(uint4*)sB0 = b0; *(uint4*)sB1 = b1;
    }
    __syncthreads();

    uint4 pa0, pa1, pb0, pb1;
    for (int ch = 0; ch < NCHUNK; ch++) {
        const int buf = ch & 1;
        const bool more = (ch + 1 < NCHUNK);
        if (more) {
            const int kb = (ch + 1) * KC;
            pa0 = *(const uint4*)(Arow0 + kb);
            pa1 = *(const uint4*)(Arow1 + kb);
            pb0 = *(const uint4*)(Brow0 + kb);
            pb1 = *(const uint4*)(Brow1 + kb);
        }

        const __nv_bfloat16* Asb = AsB + buf * 128 * PITCH;
        const __nv_bfloat16* Bsb = BsB + buf * 128 * PITCH;
        #pragma unroll
        for (int ks = 0; ks < 4; ks++) {
            const int k16 = ks * 16;
            unsigned a[2][4];
            #pragma unroll
            for (int mt = 0; mt < 2; mt++) {
                const __nv_bfloat16* base = &Asb[(warp_m + mt * 16 + g) * PITCH + k16 + 2 * tg];
                a[mt][0] = *(const unsigned*)base;
                a[mt][1] = *(const unsigned*)(base + 8 * PITCH);
                a[mt][2] = *(const unsigned*)(base + 8);
                a[mt][3] = *(const unsigned*)(base + 8 * PITCH + 8);
            }
            #pragma unroll
            for (int nt = 0; nt < 4; nt++) {
                const __nv_bfloat16* bb = &Bsb[(warp_n + nt * 8 + g) * PITCH + k16 + 2 * tg];
                unsigned b0 = *(const unsigned*)bb;
                unsigned b1 = *(const unsigned*)(bb + 8);
                #pragma unroll
                for (int mt = 0; mt < 2; mt++)
                    mma_bf16(c[mt][nt][0], c[mt][nt][1], c[mt][nt][2], c[mt][nt][3],
                             a[mt][0], a[mt][1], a[mt][2], a[mt][3], b0, b1);
            }
        }

        if (more) {
            const int nbuf = buf ^ 1;
            *(uint4*)(sA0 + nbuf * 128 * PITCH) = pa0;
            *(uint4*)(sA1 + nbuf * 128 * PITCH) = pa1;
            *(uint4*)(sB0 + nbuf * 128 * PITCH) = pb0;
            *(uint4*)(sB1 + nbuf * 128 * PITCH) = pb1;
        }
        __syncthreads();
    }

    // ---- fused epilogue: warp owns one head (32 cols = x1[16] | x2[16]) ----
    float* connOut = d_out + (size_t)NN * 128;
    const int h = half * 4 + (wrp >> 2);
    #pragma unroll
    for (int mt = 0; mt < 2; mt++) {
        #pragma unroll
        for (int hf = 0; hf < 2; hf++) {
            const int r = warp_m + mt * 16 + g + hf * 8;
            const int e = m0 + r;
            const bool ok = (e < EE);
            int srcn = 0, dstn = 0;
            if (ok) { srcn = edge_index[e]; dstn = edge_index[EE + e]; }
            float ps = 0.f;
            float cn[2][2];
            #pragma unroll
            for (int dd = 0; dd < 2; dd++) {
                float2 kv = make_float2(0.f, 0.f), qv = make_float2(0.f, 0.f);
                if (ok) {
                    kv = *(const float2*)&g_Kh[(size_t)srcn * 128 + h * 16 + dd * 8 + 2 * tg];
                    qv = *(const float2*)&g_Qh[(size_t)dstn * 128 + h * 16 + dd * 8 + 2 * tg];
                }
                #pragma unroll
                for (int cc = 0; cc < 2; cc++) {
                    const int q = hf * 2 + cc;
                    const int colA = n0 + warp_n + dd * 8 + 2 * tg + cc;
                    float x1 = c[mt][dd][q]     + bias[colA];
                    float x2 = c[mt][dd + 2][q] + bias[colA + 16];
                    float s2 = x1 * x2;
                    float sc2 = copysignf(sqrtf(fabsf(s2)), s2);
                    float cnv = sc2 + (cc ? (kv.y + qv.y) : (kv.x + qv.x));
                    cn[dd][cc] = cnv;
                    const int d = dd * 8 + 2 * tg + cc;
                    ps = fmaf(cnv, Aw[d * 8 + h], ps);
                }
            }
            ps += __shfl_xor_sync(0xffffffffu, ps, 1);
            ps += __shfl_xor_sync(0xffffffffu, ps, 2);
            if (ok) {
                *(float2*)&connOut[(size_t)e * 128 + h * 16 + 2 * tg]     = make_float2(cn[0][0], cn[0][1]);
                *(float2*)&connOut[(size_t)e * 128 + h * 16 + 8 + 2 * tg] = make_float2(cn[1][0], cn[1][1]);
                if (tg == 0) {
                    float s = fminf(fmaxf(ps, -CLAMPV), CLAMPV);
                    float eev = expf(s);
                    g_eexp[(size_t)e * 8 + h] = eev;
                    atomicAdd(&g_denom[dstn * 8 + h], eev);
                }
            }
        }
    }
}

// ---------------- aggregation: warp per edge ---------------------------------
__global__ __launch_bounds__(256) void aggregate(
    const int* __restrict__ edge_index,
    float* __restrict__ d_out)
{
    const int warp = threadIdx.x >> 5;
    const int lane = threadIdx.x & 31;
    const size_t e = (size_t)blockIdx.x * 8 + warp;
    if (e >= EE) return;

    const int src = edge_index[e];
    const int dst = edge_index[EE + e];
    const int h = lane >> 2;

    float den  = g_denom[dst * 8 + h];
    float attn = g_eexp[e * 8 + h] / (den + 1e-16f);

    const float4* Vh4   = (const float4*)g_Vh;
    const float4* conn4 = (const float4*)(d_out + (size_t)NN * 128);
    float4 v = Vh4[(size_t)src * 32 + lane];
    float4 c = conn4[e * 32 + lane];

    float4* out4 = (float4*)d_out;
    float4* row4 = (float4*)g_rowV;
    red_add_v4((float*)&out4[(size_t)dst * 32 + lane], v.x * attn, v.y * attn, v.z * attn, v.w * attn);
    red_add_v4((float*)&row4[(size_t)dst * 32 + lane], c.x * attn, c.y * attn, c.z * attn, c.w * attn);
}

// ---------------- finalize: Vo += rowV @ VeRow per head ----------------------
__global__ __launch_bounds__(128) void finalize(
    const float* __restrict__ VeRow,
    float* __restrict__ d_out)
{
    __shared__ float Vs[2048];
    const int tid = threadIdx.x;
    for (int i = tid; i < 2048; i += 128) Vs[i] = VeRow[i];
    __syncthreads();

    const int h = tid >> 4, c = tid & 15;
    const int n0 = blockIdx.x * 32;
    const int nend = (n0 + 32 < NN) ? n0 + 32 : NN;
    for (int n = n0; n < nend; n++) {
        float acc = 0.f;
        #pragma unroll
        for (int d = 0; d < 16; d++)
            acc = fmaf(g_rowV[(size_t)n * 128 + h * 16 + d], Vs[d * 128 + h * 16 + c], acc);
        d_out[(size_t)n * 128 + h * 16 + c] += acc;
    }
}

// ---------------- launch ------------------------------------------------------
#define GEMM_SM (4 * 128 * PITCH * 2)   // 73728 bytes

extern "C" void kernel_launch(void* const* d_in, const int* in_sizes, int n_in,
                              void* d_out, int out_size)
{
    const float* x    = (const float*)d_in[0];
    const float* ea   = (const float*)d_in[1];
    const int*   eidx = (const int*)  d_in[2];
    const float* WQ   = (const float*)d_in[3];
    const float* bQ   = (const float*)d_in[4];
    const float* WK   = (const float*)d_in[5];
    const float* bK   = (const float*)d_in[6];
    const float* WE   = (const float*)d_in[7];
    const float* bE   = (const float*)d_in[8];
    const float* WV   = (const float*)d_in[9];
    const float* bV   = (const float*)d_in[10];
    const float* Aw   = (const float*)d_in[11];
    const float* VeRow= (const float*)d_in[12];
    float* out = (float*)d_out;

    static bool attr_set = false;
    if (!attr_set) {
        cudaFuncSetAttribute(edge_gemm_tc,
                             cudaFuncAttributeMaxDynamicSharedMemorySize, GEMM_SM);
        attr_set = true;
    }

    zero_kernel<<<1024, 256>>>();

    // edge operand conversion (fp32 -> bf16 hi/lo tri-split), pad rows zeroed
    convert_rows<<<(EPAD * 16 + 255) / 256, 256>>>(ea, g_Ae, EE, EPAD);
    convert_W<<<(128 * 256 + 255) / 256, 256>>>(WE, g_Be, 256);

    // node GEMMs (fp32, proven): Qh mirrored into d_out, Kh, Vh
    dim3 gn((NN + 63) / 64, 3);
    node_gemm<<<gn, 256>>>(x, WQ, bQ, WK, bK, WV, bV, out);

    // edge GEMM + fused epilogue; n-half in grid.x LSB (A tile L2 reuse)
    int mtiles = (EE + 127) / 128;
    edge_gemm_tc<<<mtiles * 2, 512, GEMM_SM>>>(g_Ae, g_Be, bE, eidx, Aw, out);

    aggregate<<<(EE + 7) / 8, 256>>>(eidx, out);

    finalize<<<(NN + 31) / 32, 128>>>(VeRow, out);
}

// round 9
// speedup vs baseline: 10.1406x; 10.1406x over previous
#include <cuda_runtime.h>
#include <math.h>

#define NN 50000
#define EE 500000
#define CLAMPV 5.0f

// ---------------- scratch ----------------------------------------------------
__device__ float g_Qh[NN * 128];
__device__ float g_Kh[NN * 128];
__device__ float g_Vh[NN * 128];
__device__ float g_eexp[(size_t)EE * 8];
__device__ float g_denom[NN * 8];
__device__ float g_rowV[NN * 128];

// ---------------- helpers ----------------------------------------------------
__device__ __forceinline__ void red_add_v4(float* addr, float a, float b, float c, float d) {
    asm volatile("red.global.add.v4.f32 [%0], {%1,%2,%3,%4};"
                 :: "l"(addr), "f"(a), "f"(b), "f"(c), "f"(d) : "memory");
}

// ---------------- zero scratch ------------------------------------------------
__global__ void zero_kernel() {
    int stride = gridDim.x * blockDim.x;
    int total = NN * 128 + NN * 8;
    for (int i = blockIdx.x * blockDim.x + threadIdx.x; i < total; i += stride) {
        if (i < NN * 128) g_rowV[i] = 0.f;
        else              g_denom[i - NN * 128] = 0.f;
    }
}

// ---------------- node GEMM (fp32, proven round 1) -----------------------------
__global__ __launch_bounds__(256) void node_gemm(
    const float* __restrict__ x,
    const float* __restrict__ WQ, const float* __restrict__ bQ,
    const float* __restrict__ WK, const float* __restrict__ bK,
    const float* __restrict__ WV, const float* __restrict__ bV,
    float* __restrict__ d_out)
{
    const int which = blockIdx.y;
    const float* W    = (which == 0) ? WQ : (which == 1) ? WK : WV;
    const float* bias = (which == 0) ? bQ : (which == 1) ? bK : bV;
    float* out        = (which == 0) ? g_Qh : (which == 1) ? g_Kh : g_Vh;

    __shared__ float As[64 * 16];
    __shared__ float Bs[16 * 128];

    const int tid = threadIdx.x;
    const int tx = tid & 15, ty = tid >> 4;
    const int m0 = blockIdx.x * 64;

    const int ar = tid >> 2;
    const int ac = (tid & 3) * 4;
    const int brow = tid >> 4;
    const int bcol = (tid & 15) * 8;

    float acc[4][8];
    #pragma unroll
    for (int i = 0; i < 4; i++)
        #pragma unroll
        for (int j = 0; j < 8; j++) acc[i][j] = 0.f;

    for (int k0 = 0; k0 < 128; k0 += 16) {
        float4 av = make_float4(0.f, 0.f, 0.f, 0.f);
        int m = m0 + ar;
        if (m < NN) av = *(const float4*)&x[(size_t)m * 128 + k0 + ac];
        *(float4*)&As[ar * 16 + ac] = av;
        *(float4*)&Bs[brow * 128 + bcol]     = *(const float4*)&W[(size_t)(k0 + brow) * 128 + bcol];
        *(float4*)&Bs[brow * 128 + bcol + 4] = *(const float4*)&W[(size_t)(k0 + brow) * 128 + bcol + 4];
        __syncthreads();
        #pragma unroll
        for (int k = 0; k < 16; k++) {
            float a[4], b[8];
            #pragma unroll
            for (int i = 0; i < 4; i++) a[i] = As[(ty * 4 + i) * 16 + k];
            #pragma unroll
            for (int j = 0; j < 8; j++) b[j] = Bs[k * 128 + tx * 8 + j];
            #pragma unroll
            for (int i = 0; i < 4; i++)
                #pragma unroll
                for (int j = 0; j < 8; j++)
                    acc[i][j] = fmaf(a[i], b[j], acc[i][j]);
        }
        __syncthreads();
    }

    #pragma unroll
    for (int i = 0; i < 4; i++) {
        int m = m0 + ty * 4 + i;
        if (m >= NN) continue;
        #pragma unroll
        for (int j = 0; j < 8; j++) {
            int c = tx * 8 + j;
            float v = acc[i][j] + bias[c];
            out[(size_t)m * 128 + c] = v;
            if (which == 0) d_out[(size_t)m * 128 + c] = v;
        }
    }
}

// ---------------- edge GEMM fp32: 64(M) x 256(N), 8x8 microtile ---------------
// One CTA covers ALL 8 heads for 64 edges. ea read exactly once.
// Smem phases (separated by __syncthreads):
//   phase 1 (compute): As[64][16] @ [0,1024), Bs[16][256] @ [1024,5120) floats
//   phase 2 (epilogue): Ex[64][256] @ [0,16384) floats
//   AwS @ [16384,16512) floats (disjoint from both, loaded once).
__global__ __launch_bounds__(256) void edge_gemm_f32(
    const float* __restrict__ ea,
    const float* __restrict__ WE, const float* __restrict__ bE,
    const int* __restrict__ edge_index,
    const float* __restrict__ Aw,
    float* __restrict__ d_out)
{
    extern __shared__ float sm[];
    float* As  = sm;            // [64][16]
    float* Bs  = sm + 1024;     // [16][256]
    float* Ex  = sm;            // [64][256] (aliases As/Bs after compute)
    float* AwS = sm + 16384;    // [128]

    const int tid = threadIdx.x;
    const int tx = tid & 31, ty = tid >> 5;   // 32 x 8 thread grid
    const int m0 = blockIdx.x * 64;

    if (tid < 128) AwS[tid] = Aw[tid];

    const int ar = tid >> 2;            // 0..63
    const int ac = (tid & 3) * 4;       // 0,4,8,12
    const int brow = tid >> 4;          // 0..15
    const int bcol = (tid & 15) * 16;   // 0..240

    float acc[8][8];
    #pragma unroll
    for (int i = 0; i < 8; i++)
        #pragma unroll
        for (int j = 0; j < 8; j++) acc[i][j] = 0.f;

    for (int k0 = 0; k0 < 128; k0 += 16) {
        __syncthreads();   // previous compute done before overwriting smem
        float4 av = make_float4(0.f, 0.f, 0.f, 0.f);
        int m = m0 + ar;
        if (m < EE) av = *(const float4*)&ea[(size_t)m * 128 + k0 + ac];
        *(float4*)&As[ar * 16 + ac] = av;
        const float* wrow = &WE[(size_t)(k0 + brow) * 256 + bcol];
        #pragma unroll
        for (int q = 0; q < 4; q++)
            *(float4*)&Bs[brow * 256 + bcol + q * 4] = *(const float4*)&wrow[q * 4];
        __syncthreads();

        #pragma unroll
        for (int k = 0; k < 16; k++) {
            float a[8];
            #pragma unroll
            for (int i = 0; i < 8; i++) a[i] = As[(ty * 8 + i) * 16 + k];   // broadcast
            float4 b0 = *(const float4*)&Bs[k * 256 + tx * 8];
            float4 b1 = *(const float4*)&Bs[k * 256 + tx * 8 + 4];
            const float b[8] = {b0.x, b0.y, b0.z, b0.w, b1.x, b1.y, b1.z, b1.w};
            #pragma unroll
            for (int i = 0; i < 8; i++)
                #pragma unroll
                for (int j = 0; j < 8; j++)
                    acc[i][j] = fmaf(a[i], b[j], acc[i][j]);
        }
    }
    __syncthreads();

    // ---- stash Ex (+bias) ----
    #pragma unroll
    for (int i = 0; i < 8; i++) {
        int r = ty * 8 + i;
        #pragma unroll
        for (int j = 0; j < 8; j++) {
            int c = tx * 8 + j;
            Ex[r * 256 + c] = acc[i][j] + bE[c];
        }
    }
    __syncthreads();

    float* connOut = d_out + (size_t)NN * 128;

    // ---- conn: 64 edges * 8 heads * 16 dims = 8192 values, 32 per thread ----
    for (int idx = tid; idx < 64 * 128; idx += 256) {
        int el  = idx >> 7;
        int rem = idx & 127;
        int gg  = rem >> 4;     // head 0..7
        int d   = rem & 15;
        int e   = m0 + el;
        float x1 = Ex[el * 256 + gg * 32 + d];
        float x2 = Ex[el * 256 + gg * 32 + 16 + d];
        float s2 = x1 * x2;
        float sc2 = copysignf(sqrtf(fabsf(s2)), s2);
        if (e < EE) {
            int src = edge_index[e];
            int dst = edge_index[EE + e];
            float conn = g_Kh[(size_t)src * 128 + gg * 16 + d]
                       + g_Qh[(size_t)dst * 128 + gg * 16 + d] + sc2;
            connOut[(size_t)e * 128 + gg * 16 + d] = conn;
            Ex[el * 256 + gg * 32 + d] = conn;
        }
    }
    __syncthreads();

    // ---- score per (edge, head): 512 tasks, 2 per thread ----
    #pragma unroll
    for (int it = 0; it < 2; it++) {
        int t  = tid + it * 256;
        int el = t >> 3;
        int gg = t & 7;
        int e  = m0 + el;
        if (e < EE) {
            float s = 0.f;
            #pragma unroll
            for (int d = 0; d < 16; d++)
                s = fmaf(Ex[el * 256 + gg * 32 + d], AwS[d * 8 + gg], s);
            s = fminf(fmaxf(s, -CLAMPV), CLAMPV);
            float eev = expf(s);
            g_eexp[(size_t)e * 8 + gg] = eev;
            int dst = edge_index[EE + e];
            atomicAdd(&g_denom[dst * 8 + gg], eev);
        }
    }
}

// ---------------- aggregation: warp per edge (proven) -------------------------
__global__ __launch_bounds__(256) void aggregate(
    const int* __restrict__ edge_index,
    float* __restrict__ d_out)
{
    const int warp = threadIdx.x >> 5;
    const int lane = threadIdx.x & 31;
    const size_t e = (size_t)blockIdx.x * 8 + warp;
    if (e >= EE) return;

    const int src = edge_index[e];
    const int dst = edge_index[EE + e];
    const int h = lane >> 2;

    float den  = g_denom[dst * 8 + h];
    float attn = g_eexp[e * 8 + h] / (den + 1e-16f);

    const float4* Vh4   = (const float4*)g_Vh;
    const float4* conn4 = (const float4*)(d_out + (size_t)NN * 128);
    float4 v = Vh4[(size_t)src * 32 + lane];
    float4 c = conn4[e * 32 + lane];

    float4* out4 = (float4*)d_out;
    float4* row4 = (float4*)g_rowV;
    red_add_v4((float*)&out4[(size_t)dst * 32 + lane], v.x * attn, v.y * attn, v.z * attn, v.w * attn);
    red_add_v4((float*)&row4[(size_t)dst * 32 + lane], c.x * attn, c.y * attn, c.z * attn, c.w * attn);
}

// ---------------- finalize: Vo += rowV @ VeRow per head (proven) --------------
__global__ __launch_bounds__(128) void finalize(
    const float* __restrict__ VeRow,
    float* __restrict__ d_out)
{
    __shared__ float Vs[2048];
    const int tid = threadIdx.x;
    for (int i = tid; i < 2048; i += 128) Vs[i] = VeRow[i];
    __syncthreads();

    const int h = tid >> 4, c = tid & 15;
    const int n0 = blockIdx.x * 32;
    const int nend = (n0 + 32 < NN) ? n0 + 32 : NN;
    for (int n = n0; n < nend; n++) {
        float acc = 0.f;
        #pragma unroll
        for (int d = 0; d < 16; d++)
            acc = fmaf(g_rowV[(size_t)n * 128 + h * 16 + d], Vs[d * 128 + h * 16 + c], acc);
        d_out[(size_t)n * 128 + h * 16 + c] += acc;
    }
}

// ---------------- launch ------------------------------------------------------
#define EDGE_SM ((64 * 256 + 128) * 4)   // Ex + AwS = 66048 bytes

extern "C" void kernel_launch(void* const* d_in, const int* in_sizes, int n_in,
                              void* d_out, int out_size)
{
    const float* x    = (const float*)d_in[0];
    const float* ea   = (const float*)d_in[1];
    const int*   eidx = (const int*)  d_in[2];
    const float* WQ   = (const float*)d_in[3];
    const float* bQ   = (const float*)d_in[4];
    const float* WK   = (const float*)d_in[5];
    const float* bK   = (const float*)d_in[6];
    const float* WE   = (const float*)d_in[7];
    const float* bE   = (const float*)d_in[8];
    const float* WV   = (const float*)d_in[9];
    const float* bV   = (const float*)d_in[10];
    const float* Aw   = (const float*)d_in[11];
    const float* VeRow= (const float*)d_in[12];
    float* out = (float*)d_out;

    static bool attr_set = false;
    if (!attr_set) {
        cudaFuncSetAttribute(edge_gemm_f32,
                             cudaFuncAttributeMaxDynamicSharedMemorySize, EDGE_SM);
        attr_set = true;
    }

    zero_kernel<<<1024, 256>>>();

    dim3 gn((NN + 63) / 64, 3);
    node_gemm<<<gn, 256>>>(x, WQ, bQ, WK, bK, WV, bV, out);

    edge_gemm_f32<<<(EE + 63) / 64, 256, EDGE_SM>>>(ea, WE, bE, eidx, Aw, out);

    aggregate<<<(EE + 7) / 8, 256>>>(eidx, out);

    finalize<<<(NN + 31) / 32, 128>>>(VeRow, out);
}